// round 7
// baseline (speedup 1.0000x reference)
#include <cuda_runtime.h>
#include <math.h>

#define NN 100000
#define EE 1700000
#define GG 1024

// ---------------- scratch ----------------
__device__ float    g_va_src[28];
__device__ float    g_va_dst[28];
__device__ float    g_W2T[32 * 128];    // transposed W2: [c][k]
__device__ float    g_es1 [NN * 4];
__device__ float    g_ed1 [NN * 4];
__device__ float    g_acc [NN * 32];    // per-dst: [h*7+i]=Σ p*x_i ; [28+h]=Σ p
__device__ float    g_h2  [NN * 32];
__device__ float    g_es2 [NN];
__device__ float    g_ed2 [NN];
__device__ float    g_den2[NN];
__device__ float    g_out2[NN * 32];
__device__ float    g_msum[GG * 32];
__device__ unsigned g_mmax[GG * 32];
__device__ float    g_cnt [GG];

// ---------------- helpers ----------------
__device__ __forceinline__ unsigned fenc(float f) {
    unsigned u = __float_as_uint(f);
    return (u & 0x80000000u) ? ~u : (u | 0x80000000u);
}
__device__ __forceinline__ float fdec(unsigned u) {
    return __uint_as_float((u & 0x80000000u) ? (u & 0x7FFFFFFFu) : ~u);
}
__device__ __forceinline__ float lrelu(float v) { return v > 0.f ? v : 0.2f * v; }
__device__ __forceinline__ float elu(float v)   { return v > 0.f ? v : __expf(v) - 1.f; }

// ---------------- K0: va = W1 @ a ; W2 transpose ----------------
__global__ void k_va(const float* __restrict__ W1, const float* __restrict__ as1,
                     const float* __restrict__ ad1, const float* __restrict__ W2) {
    int t = threadIdx.x;  // 128
    if (t < 28) {
        int i = t >> 2, h = t & 3;
        float ss = 0.f, dd = 0.f;
        #pragma unroll
        for (int c = 0; c < 32; c++) {
            float w = W1[i * 128 + h * 32 + c];
            ss += w * as1[h * 32 + c];
            dd += w * ad1[h * 32 + c];
        }
        g_va_src[i * 4 + h] = ss;
        g_va_dst[i * 4 + h] = dd;
    }
    for (int i = t; i < 4096; i += 128) {
        int k = i >> 5, c = i & 31;
        g_W2T[c * 128 + k] = W2[i];
    }
}

// ---------------- K1: per-node logits + self-loop-seeded accumulator ----------------
__global__ void k_node1(const float* __restrict__ x, int N) {
    int n = blockIdx.x * blockDim.x + threadIdx.x;
    if (n >= N) return;
    float xv[7];
    #pragma unroll
    for (int i = 0; i < 7; i++) xv[i] = x[n * 7 + i];
    float es[4], ed[4];
    #pragma unroll
    for (int h = 0; h < 4; h++) {
        float s = 0.f, d = 0.f;
        #pragma unroll
        for (int i = 0; i < 7; i++) {
            s += xv[i] * g_va_src[i * 4 + h];
            d += xv[i] * g_va_dst[i * 4 + h];
        }
        es[h] = s; ed[h] = d;
    }
    *(float4*)&g_es1[n * 4] = make_float4(es[0], es[1], es[2], es[3]);
    *(float4*)&g_ed1[n * 4] = make_float4(ed[0], ed[1], ed[2], ed[3]);
    float p[4];
    #pragma unroll
    for (int h = 0; h < 4; h++) p[h] = __expf(lrelu(es[h] + ed[h]));
    float a[32];
    #pragma unroll
    for (int h = 0; h < 4; h++) {
        #pragma unroll
        for (int i = 0; i < 7; i++) a[h * 7 + i] = p[h] * xv[i];
        a[28 + h] = p[h];
    }
    #pragma unroll
    for (int q = 0; q < 8; q++)
        *(float4*)&g_acc[n * 32 + q * 4] = make_float4(a[q*4], a[q*4+1], a[q*4+2], a[q*4+3]);
}

// ---------------- K2: layer1 edge aggregation, two-phase ----------------
// Phase 1: thread-per-edge computes all 32 accumulator values into smem.
// Phase 2: 8 lanes/edge, LDS.128 + RED.128.
__global__ __launch_bounds__(256) void k_agg1(
        const float* __restrict__ x, const int* __restrict__ src,
        const int* __restrict__ dst, int E) {
    __shared__ float sv[256][32];
    __shared__ int   sdst[256];
    int t = threadIdx.x;
    int ebase = blockIdx.x << 8;
    int e = ebase + t;
    if (e < E) {
        int s = src[e], d = dst[e];
        const float4 es = *(const float4*)&g_es1[s * 4];
        const float4 ed = *(const float4*)&g_ed1[d * 4];
        float p[4];
        p[0] = __expf(lrelu(es.x + ed.x));
        p[1] = __expf(lrelu(es.y + ed.y));
        p[2] = __expf(lrelu(es.z + ed.z));
        p[3] = __expf(lrelu(es.w + ed.w));
        float xv[7];
        #pragma unroll
        for (int i = 0; i < 7; i++) xv[i] = __ldg(&x[s * 7 + i]);
        #pragma unroll
        for (int h = 0; h < 4; h++) {
            #pragma unroll
            for (int i = 0; i < 7; i++) sv[t][h * 7 + i] = p[h] * xv[i];
            sv[t][28 + h] = p[h];
        }
        sdst[t] = d;
    }
    __syncthreads();
    int lane = t & 7, eg = t >> 3;       // 32 groups of 8 lanes
    int eend = min(256, E - ebase);
    #pragma unroll 2
    for (int r = 0; r < 8; r++) {
        int le = eg * 8 + r;
        if (le >= eend) break;
        int d = sdst[le];
        float4 v = *(const float4*)&sv[le][lane * 4];
        atomicAdd((float4*)&g_acc[d * 32 + lane * 4], v);
    }
}

// ---------------- K3: acc -> act1 -> h2 -> logits -> self2 seed (fused) ----------------
// 256 threads, 32 nodes/block, warp owns 4 nodes. W2T from global (L1-hot), LDG.128.
__global__ __launch_bounds__(256, 6) void k_finish1(
        const float* __restrict__ W1, const float* __restrict__ b1,
        const float* __restrict__ as2, const float* __restrict__ ad2, int N) {
    __shared__ float sW1[896];
    __shared__ float sb1[128];
    __shared__ float sas[32], sad[32];
    __shared__ float sacc[32][32];
    __shared__ float sact[32][128];
    int t = threadIdx.x;
    int w = t >> 5, lane = t & 31;
    for (int i = t; i < 896; i += 256) sW1[i] = W1[i];
    if (t < 128) sb1[t] = b1[t];
    if (t < 32) { sas[t] = as2[t]; sad[t] = ad2[t]; }

    int nbase = blockIdx.x * 32;
    for (int i = t; i < 1024; i += 256) {
        int nl = i >> 5, c = i & 31;
        int n = nbase + nl;
        sacc[nl][c] = (n < N) ? g_acc[n * 32 + c] : 1.f;
    }
    __syncthreads();

    // Stage B: act1 for this warp's 4 nodes
    #pragma unroll
    for (int j = 0; j < 4; j++) {
        int nl = w * 4 + j;
        #pragma unroll
        for (int q = 0; q < 4; q++) {
            float s = 0.f;
            #pragma unroll
            for (int i = 0; i < 7; i++)
                s += sacc[nl][q * 7 + i] * sW1[i * 128 + q * 32 + lane];
            float den = sacc[nl][28 + q] + 1e-16f;
            sact[nl][q * 32 + lane] = elu(__fdividef(s, den) + sb1[q * 32 + lane]);
        }
    }
    __syncwarp();   // warp reads only its own sact rows below

    // Stage C: h2 = act1 @ W2; both operands via 128-bit loads
    float h2a[4] = {0.f, 0.f, 0.f, 0.f};
    const float* wrow = &g_W2T[lane * 128];
    #pragma unroll 8
    for (int q = 0; q < 32; q++) {
        float4 wv = *(const float4*)&wrow[q * 4];
        #pragma unroll
        for (int j = 0; j < 4; j++) {
            float4 av = *(const float4*)&sact[w * 4 + j][q * 4];
            h2a[j] += av.x * wv.x + av.y * wv.y + av.z * wv.z + av.w * wv.w;
        }
    }

    // Epilogue: logits + fused layer2 self-loop seed
    #pragma unroll
    for (int j = 0; j < 4; j++) {
        int n = nbase + w * 4 + j;
        if (n >= N) continue;
        float h2 = h2a[j];
        float e_s = h2 * sas[lane], e_d = h2 * sad[lane];
        #pragma unroll
        for (int o = 16; o; o >>= 1) {
            e_s += __shfl_xor_sync(0xFFFFFFFFu, e_s, o);
            e_d += __shfl_xor_sync(0xFFFFFFFFu, e_d, o);
        }
        float p = __expf(lrelu(e_s + e_d));
        g_h2[n * 32 + lane] = h2;
        g_out2[n * 32 + lane] = p * h2;
        if (lane == 0) { g_es2[n] = e_s; g_ed2[n] = e_d; g_den2[n] = p; }
    }
}

// ---------------- K5: layer2 edge aggregation, two-phase ----------------
__global__ __launch_bounds__(256) void k_agg2(
        const int* __restrict__ src, const int* __restrict__ dst, int E) {
    __shared__ float sp[256];
    __shared__ int   ssrc[256];
    __shared__ int   sdst[256];
    int t = threadIdx.x;
    int ebase = blockIdx.x << 8;
    int e = ebase + t;
    if (e < E) {
        int s = src[e], d = dst[e];
        float p = __expf(lrelu(g_es2[s] + g_ed2[d]));
        atomicAdd(&g_den2[d], p);
        sp[t] = p; ssrc[t] = s; sdst[t] = d;
    }
    __syncthreads();
    int lane = t & 7, eg = t >> 3;
    int eend = min(256, E - ebase);
    #pragma unroll 2
    for (int r = 0; r < 8; r++) {
        int le = eg * 8 + r;
        if (le >= eend) break;
        int s = ssrc[le], d = sdst[le];
        float p = sp[le];
        float4 hv = *(const float4*)&g_h2[s * 32 + lane * 4];
        atomicAdd((float4*)&g_out2[d * 32 + lane * 4],
                  make_float4(hv.x * p, hv.y * p, hv.z * p, hv.w * p));
    }
}

// ---------------- K6: init pools ----------------
__global__ void k_pool_init() {
    int i = blockIdx.x * blockDim.x + threadIdx.x;
    if (i < GG * 32) { g_msum[i] = 0.f; g_mmax[i] = 0u; }
    if (i < GG) g_cnt[i] = 0.f;
}

// ---------------- K7: finalize layer2 act, pools ----------------
__global__ void k_pool(const float* __restrict__ b2, const int* __restrict__ batch, int N) {
    int gid = blockIdx.x * blockDim.x + threadIdx.x;
    int n = gid >> 5, c = gid & 31;
    if (n >= N) return;
    float v = elu(__fdividef(g_out2[n * 32 + c], g_den2[n] + 1e-16f) + b2[c]);
    int g = batch[n];
    atomicAdd(&g_msum[g * 32 + c], v);
    atomicMax(&g_mmax[g * 32 + c], fenc(v));
    if (c == 0) atomicAdd(&g_cnt[g], 1.f);
}

// ---------------- K8: readout MLP ----------------
__global__ void k_mlp(const float* __restrict__ Wm1, const float* __restrict__ bm1,
                      const float* __restrict__ Wm2, const float* __restrict__ bm2,
                      float* __restrict__ out) {
    __shared__ float gv[64];
    __shared__ float red[64];
    int g = blockIdx.x, j = threadIdx.x;  // 64
    if (j < 32) gv[j] = g_msum[g * 32 + j] / g_cnt[g];
    else        gv[j] = fdec(g_mmax[g * 32 + (j - 32)]);
    __syncthreads();
    float acc = bm1[j];
    #pragma unroll 8
    for (int i = 0; i < 64; i++) acc += gv[i] * Wm1[i * 64 + j];
    red[j] = fmaxf(acc, 0.f) * Wm2[j];
    __syncthreads();
    for (int o = 32; o; o >>= 1) {
        if (j < o) red[j] += red[j + o];
        __syncthreads();
    }
    if (j == 0) out[g] = red[0] + bm2[0];
}

// ---------------- host ----------------
extern "C" void kernel_launch(void* const* d_in, const int* in_sizes, int n_in,
                              void* d_out, int out_size) {
    const float* x    = (const float*)d_in[0];
    const int*   ei   = (const int*)  d_in[1];
    const int*   bat  = (const int*)  d_in[2];
    const float* W1   = (const float*)d_in[3];
    const float* as1  = (const float*)d_in[4];
    const float* ad1  = (const float*)d_in[5];
    const float* b1   = (const float*)d_in[6];
    const float* W2   = (const float*)d_in[7];
    const float* as2  = (const float*)d_in[8];
    const float* ad2  = (const float*)d_in[9];
    const float* b2   = (const float*)d_in[10];
    const float* Wm1  = (const float*)d_in[11];
    const float* bm1  = (const float*)d_in[12];
    const float* Wm2  = (const float*)d_in[13];
    const float* bm2  = (const float*)d_in[14];
    float* out = (float*)d_out;

    int N = in_sizes[0] / 7;
    int E = in_sizes[1] / 2;
    const int* src = ei;
    const int* dst = ei + E;

    k_va<<<1, 128>>>(W1, as1, ad1, W2);
    k_node1<<<(N + 255) / 256, 256>>>(x, N);
    k_agg1<<<(E + 255) / 256, 256>>>(x, src, dst, E);
    k_finish1<<<(N + 31) / 32, 256>>>(W1, b1, as2, ad2, N);
    k_agg2<<<(E + 255) / 256, 256>>>(src, dst, E);
    k_pool_init<<<(GG * 32 + 255) / 256, 256>>>();
    {
        long long thr = (long long)N * 32;
        k_pool<<<(int)((thr + 255) / 256), 256>>>(b2, bat, N);
    }
    k_mlp<<<GG, 64>>>(Wm1, bm1, Wm2, bm2, out);
}

// round 8
// speedup vs baseline: 1.7828x; 1.7828x over previous
#include <cuda_runtime.h>
#include <math.h>

#define NN 100000
#define EE 1700000
#define GG 1024

// ---------------- scratch ----------------
__device__ float    g_va_src[28];
__device__ float    g_va_dst[28];
__device__ float    g_es1 [NN * 4];
__device__ float    g_ed1 [NN * 4];
__device__ float    g_acc [NN * 32];    // per-dst: [h*7+i]=Σ p*x_i ; [28+h]=Σ p
__device__ float    g_h2  [NN * 32];
__device__ float    g_es2 [NN];
__device__ float    g_ed2 [NN];
__device__ float    g_den2[NN];
__device__ float    g_out2[NN * 32];
__device__ float    g_msum[GG * 32];
__device__ unsigned g_mmax[GG * 32];
__device__ float    g_cnt [GG];

// ---------------- helpers ----------------
__device__ __forceinline__ unsigned fenc(float f) {
    unsigned u = __float_as_uint(f);
    return (u & 0x80000000u) ? ~u : (u | 0x80000000u);
}
__device__ __forceinline__ float fdec(unsigned u) {
    return __uint_as_float((u & 0x80000000u) ? (u & 0x7FFFFFFFu) : ~u);
}
__device__ __forceinline__ float lrelu(float v) { return v > 0.f ? v : 0.2f * v; }
__device__ __forceinline__ float elu(float v)   { return v > 0.f ? v : __expf(v) - 1.f; }

// ---------------- K0: va = W1 @ a (7x4 each) ----------------
__global__ void k_va(const float* __restrict__ W1, const float* __restrict__ as1,
                     const float* __restrict__ ad1) {
    int t = threadIdx.x;  // 32
    if (t < 28) {
        int i = t >> 2, h = t & 3;
        float ss = 0.f, dd = 0.f;
        #pragma unroll
        for (int c = 0; c < 32; c++) {
            float w = W1[i * 128 + h * 32 + c];
            ss += w * as1[h * 32 + c];
            dd += w * ad1[h * 32 + c];
        }
        g_va_src[i * 4 + h] = ss;
        g_va_dst[i * 4 + h] = dd;
    }
}

// ---------------- K1: per-node logits + self-loop-seeded accumulator ----------------
__global__ void k_node1(const float* __restrict__ x, int N) {
    int n = blockIdx.x * blockDim.x + threadIdx.x;
    if (n >= N) return;
    float xv[7];
    #pragma unroll
    for (int i = 0; i < 7; i++) xv[i] = x[n * 7 + i];
    float es[4], ed[4];
    #pragma unroll
    for (int h = 0; h < 4; h++) {
        float s = 0.f, d = 0.f;
        #pragma unroll
        for (int i = 0; i < 7; i++) {
            s += xv[i] * g_va_src[i * 4 + h];
            d += xv[i] * g_va_dst[i * 4 + h];
        }
        es[h] = s; ed[h] = d;
    }
    *(float4*)&g_es1[n * 4] = make_float4(es[0], es[1], es[2], es[3]);
    *(float4*)&g_ed1[n * 4] = make_float4(ed[0], ed[1], ed[2], ed[3]);
    float p[4];
    #pragma unroll
    for (int h = 0; h < 4; h++) p[h] = __expf(lrelu(es[h] + ed[h]));
    float a[32];
    #pragma unroll
    for (int h = 0; h < 4; h++) {
        #pragma unroll
        for (int i = 0; i < 7; i++) a[h * 7 + i] = p[h] * xv[i];
        a[28 + h] = p[h];
    }
    #pragma unroll
    for (int q = 0; q < 8; q++)
        *(float4*)&g_acc[n * 32 + q * 4] = make_float4(a[q*4], a[q*4+1], a[q*4+2], a[q*4+3]);
}

// ---------------- K2: layer1 edge aggregation, two-phase (R6 version) ----------------
__global__ __launch_bounds__(256) void k_agg1(
        const float* __restrict__ x, const int* __restrict__ src,
        const int* __restrict__ dst, int E) {
    __shared__ float sp[256 * 4];
    __shared__ int   ssrc[256];
    __shared__ int   sdst[256];
    int t = threadIdx.x;
    int ebase = blockIdx.x << 8;
    int e = ebase + t;
    if (e < E) {
        int s = src[e], d = dst[e];
        const float4 es = *(const float4*)&g_es1[s * 4];
        const float4 ed = *(const float4*)&g_ed1[d * 4];
        sp[t * 4 + 0] = __expf(lrelu(es.x + ed.x));
        sp[t * 4 + 1] = __expf(lrelu(es.y + ed.y));
        sp[t * 4 + 2] = __expf(lrelu(es.z + ed.z));
        sp[t * 4 + 3] = __expf(lrelu(es.w + ed.w));
        ssrc[t] = s; sdst[t] = d;
    }
    __syncthreads();
    int lane = t & 7, eg = t >> 3;       // 32 groups of 8 lanes
    int eend = min(256, E - ebase);
    #pragma unroll 2
    for (int r = 0; r < 8; r++) {
        int le = eg * 8 + r;
        if (le >= eend) break;
        int s = ssrc[le], d = sdst[le];
        float p[4] = { sp[le*4], sp[le*4+1], sp[le*4+2], sp[le*4+3] };
        const float* xs = &x[s * 7];
        float v[4];
        #pragma unroll
        for (int j = 0; j < 4; j++) {
            int idx = lane * 4 + j;
            int h7 = (idx * 9363) >> 16;  // idx/7 (exact for idx<32)
            int i7 = idx - h7 * 7;
            v[j] = (idx < 28) ? p[h7] * __ldg(&xs[i7]) : p[idx - 28];
        }
        atomicAdd((float4*)&g_acc[d * 32 + lane * 4], make_float4(v[0], v[1], v[2], v[3]));
    }
}

// ---------------- K3: acc -> act1 -> h2 -> logits -> self2 seed (fused) ----------------
// 256 threads, 32 nodes/block, warp owns 4 nodes. act staged TRANSPOSED (pad 36):
// Stage C per k: 1 coalesced LDG(W2) + 1 broadcast LDS.128 + 4 FFMA.
__global__ __launch_bounds__(256, 6) void k_finish1(
        const float* __restrict__ W1, const float* __restrict__ b1,
        const float* __restrict__ W2, const float* __restrict__ as2,
        const float* __restrict__ ad2, int N) {
    __shared__ float sW1[896];
    __shared__ float sb1[128];
    __shared__ float sas[32], sad[32];
    __shared__ float sacc[32][32];
    __shared__ float sactT[128][36];     // [channel][node]; pad 36 -> 4-way write conflicts only
    int t = threadIdx.x;
    int w = t >> 5, lane = t & 31;
    for (int i = t; i < 896; i += 256) sW1[i] = W1[i];
    if (t < 128) sb1[t] = b1[t];
    if (t < 32) { sas[t] = as2[t]; sad[t] = ad2[t]; }

    int nbase = blockIdx.x * 32;
    for (int i = t; i < 1024; i += 256) {
        int nl = i >> 5, c = i & 31;
        int n = nbase + nl;
        sacc[nl][c] = (n < N) ? g_acc[n * 32 + c] : 1.f;
    }
    __syncthreads();

    // Stage B: act1 for this warp's 4 nodes, written transposed
    #pragma unroll
    for (int j = 0; j < 4; j++) {
        int nl = w * 4 + j;
        #pragma unroll
        for (int q = 0; q < 4; q++) {
            float s = 0.f;
            #pragma unroll
            for (int i = 0; i < 7; i++)
                s += sacc[nl][q * 7 + i] * sW1[i * 128 + q * 32 + lane];
            float den = sacc[nl][28 + q] + 1e-16f;
            sactT[q * 32 + lane][nl] = elu(__fdividef(s, den) + sb1[q * 32 + lane]);
        }
    }
    __syncwarp();   // warp w writes & reads only columns [w*4, w*4+4)

    // Stage C: h2 = act1 @ W2
    float h2a[4] = {0.f, 0.f, 0.f, 0.f};
    #pragma unroll 4
    for (int k = 0; k < 128; k++) {
        float wv = __ldg(&W2[k * 32 + lane]);
        float4 av = *(const float4*)&sactT[k][w * 4];
        h2a[0] += av.x * wv; h2a[1] += av.y * wv;
        h2a[2] += av.z * wv; h2a[3] += av.w * wv;
    }

    // Epilogue: logits + fused layer2 self-loop seed
    #pragma unroll
    for (int j = 0; j < 4; j++) {
        int n = nbase + w * 4 + j;
        if (n >= N) continue;
        float h2 = h2a[j];
        float e_s = h2 * sas[lane], e_d = h2 * sad[lane];
        #pragma unroll
        for (int o = 16; o; o >>= 1) {
            e_s += __shfl_xor_sync(0xFFFFFFFFu, e_s, o);
            e_d += __shfl_xor_sync(0xFFFFFFFFu, e_d, o);
        }
        float p = __expf(lrelu(e_s + e_d));
        g_h2[n * 32 + lane] = h2;
        g_out2[n * 32 + lane] = p * h2;
        if (lane == 0) { g_es2[n] = e_s; g_ed2[n] = e_d; g_den2[n] = p; }
    }
}

// ---------------- K5: layer2 edge aggregation, two-phase ----------------
__global__ __launch_bounds__(256) void k_agg2(
        const int* __restrict__ src, const int* __restrict__ dst, int E) {
    __shared__ float sp[256];
    __shared__ int   ssrc[256];
    __shared__ int   sdst[256];
    int t = threadIdx.x;
    int ebase = blockIdx.x << 8;
    int e = ebase + t;
    if (e < E) {
        int s = src[e], d = dst[e];
        float p = __expf(lrelu(g_es2[s] + g_ed2[d]));
        atomicAdd(&g_den2[d], p);
        sp[t] = p; ssrc[t] = s; sdst[t] = d;
    }
    __syncthreads();
    int lane = t & 7, eg = t >> 3;
    int eend = min(256, E - ebase);
    #pragma unroll 2
    for (int r = 0; r < 8; r++) {
        int le = eg * 8 + r;
        if (le >= eend) break;
        int s = ssrc[le], d = sdst[le];
        float p = sp[le];
        float4 hv = *(const float4*)&g_h2[s * 32 + lane * 4];
        atomicAdd((float4*)&g_out2[d * 32 + lane * 4],
                  make_float4(hv.x * p, hv.y * p, hv.z * p, hv.w * p));
    }
}

// ---------------- K6: init pools ----------------
__global__ void k_pool_init() {
    int i = blockIdx.x * blockDim.x + threadIdx.x;
    if (i < GG * 32) { g_msum[i] = 0.f; g_mmax[i] = 0u; }
    if (i < GG) g_cnt[i] = 0.f;
}

// ---------------- K7: finalize layer2 act, pools ----------------
__global__ void k_pool(const float* __restrict__ b2, const int* __restrict__ batch, int N) {
    int gid = blockIdx.x * blockDim.x + threadIdx.x;
    int n = gid >> 5, c = gid & 31;
    if (n >= N) return;
    float v = elu(__fdividef(g_out2[n * 32 + c], g_den2[n] + 1e-16f) + b2[c]);
    int g = batch[n];
    atomicAdd(&g_msum[g * 32 + c], v);
    atomicMax(&g_mmax[g * 32 + c], fenc(v));
    if (c == 0) atomicAdd(&g_cnt[g], 1.f);
}

// ---------------- K8: readout MLP ----------------
__global__ void k_mlp(const float* __restrict__ Wm1, const float* __restrict__ bm1,
                      const float* __restrict__ Wm2, const float* __restrict__ bm2,
                      float* __restrict__ out) {
    __shared__ float gv[64];
    __shared__ float red[64];
    int g = blockIdx.x, j = threadIdx.x;  // 64
    if (j < 32) gv[j] = g_msum[g * 32 + j] / g_cnt[g];
    else        gv[j] = fdec(g_mmax[g * 32 + (j - 32)]);
    __syncthreads();
    float acc = bm1[j];
    #pragma unroll 8
    for (int i = 0; i < 64; i++) acc += gv[i] * Wm1[i * 64 + j];
    red[j] = fmaxf(acc, 0.f) * Wm2[j];
    __syncthreads();
    for (int o = 32; o; o >>= 1) {
        if (j < o) red[j] += red[j + o];
        __syncthreads();
    }
    if (j == 0) out[g] = red[0] + bm2[0];
}

// ---------------- host ----------------
extern "C" void kernel_launch(void* const* d_in, const int* in_sizes, int n_in,
                              void* d_out, int out_size) {
    const float* x    = (const float*)d_in[0];
    const int*   ei   = (const int*)  d_in[1];
    const int*   bat  = (const int*)  d_in[2];
    const float* W1   = (const float*)d_in[3];
    const float* as1  = (const float*)d_in[4];
    const float* ad1  = (const float*)d_in[5];
    const float* b1   = (const float*)d_in[6];
    const float* W2   = (const float*)d_in[7];
    const float* as2  = (const float*)d_in[8];
    const float* ad2  = (const float*)d_in[9];
    const float* b2   = (const float*)d_in[10];
    const float* Wm1  = (const float*)d_in[11];
    const float* bm1  = (const float*)d_in[12];
    const float* Wm2  = (const float*)d_in[13];
    const float* bm2  = (const float*)d_in[14];
    float* out = (float*)d_out;

    int N = in_sizes[0] / 7;
    int E = in_sizes[1] / 2;
    const int* src = ei;
    const int* dst = ei + E;

    k_va<<<1, 32>>>(W1, as1, ad1);
    k_node1<<<(N + 255) / 256, 256>>>(x, N);
    k_agg1<<<(E + 255) / 256, 256>>>(x, src, dst, E);
    k_finish1<<<(N + 31) / 32, 256>>>(W1, b1, W2, as2, ad2, N);
    k_agg2<<<(E + 255) / 256, 256>>>(src, dst, E);
    k_pool_init<<<(GG * 32 + 255) / 256, 256>>>();
    {
        long long thr = (long long)N * 32;
        k_pool<<<(int)((thr + 255) / 256), 256>>>(b2, bat, N);
    }
    k_mlp<<<GG, 64>>>(Wm1, bm1, Wm2, bm2, out);
}

// round 9
// speedup vs baseline: 1.8072x; 1.0137x over previous
#include <cuda_runtime.h>
#include <math.h>

#define NN 100000
#define EE 1700000
#define GG 1024

// ---------------- scratch ----------------
__device__ float    g_es1 [NN * 4];
__device__ float    g_ed1 [NN * 4];
__device__ float    g_acc [NN * 32];    // per-dst: [h*7+i]=Σ p*x_i ; [28+h]=Σ p
__device__ float    g_h2  [NN * 32];
__device__ float    g_es2 [NN];
__device__ float    g_ed2 [NN];
__device__ float    g_den2[NN];
__device__ float    g_out2[NN * 32];
__device__ float    g_msum[GG * 32];
__device__ unsigned g_mmax[GG * 32];
__device__ float    g_cnt [GG];

// ---------------- helpers ----------------
__device__ __forceinline__ unsigned fenc(float f) {
    unsigned u = __float_as_uint(f);
    return (u & 0x80000000u) ? ~u : (u | 0x80000000u);
}
__device__ __forceinline__ float fdec(unsigned u) {
    return __uint_as_float((u & 0x80000000u) ? (u & 0x7FFFFFFFu) : ~u);
}
__device__ __forceinline__ float lrelu(float v) { return v > 0.f ? v : 0.2f * v; }
__device__ __forceinline__ float elu(float v)   { return v > 0.f ? v : __expf(v) - 1.f; }

// ---------------- K1: per-node logits + self-loop seed (va + pool-init fused) ----------------
__global__ __launch_bounds__(256) void k_node1(
        const float* __restrict__ x, const float* __restrict__ W1,
        const float* __restrict__ as1, const float* __restrict__ ad1, int N) {
    __shared__ float sva_s[28], sva_d[28];
    int t = threadIdx.x;
    if (t < 28) {
        int i = t >> 2, h = t & 3;
        float ss = 0.f, dd = 0.f;
        #pragma unroll
        for (int c = 0; c < 32; c++) {
            float w = W1[i * 128 + h * 32 + c];
            ss += w * as1[h * 32 + c];
            dd += w * ad1[h * 32 + c];
        }
        sva_s[i * 4 + h] = ss;
        sva_d[i * 4 + h] = dd;
    }
    int gid = blockIdx.x * 256 + t;
    // fold pool init (pools written only by k_pool, much later)
    if (gid < GG * 32) { g_msum[gid] = 0.f; g_mmax[gid] = 0u; }
    if (gid < GG) g_cnt[gid] = 0.f;
    __syncthreads();

    int n = gid;
    if (n >= N) return;
    float xv[7];
    #pragma unroll
    for (int i = 0; i < 7; i++) xv[i] = x[n * 7 + i];
    float es[4], ed[4];
    #pragma unroll
    for (int h = 0; h < 4; h++) {
        float s = 0.f, d = 0.f;
        #pragma unroll
        for (int i = 0; i < 7; i++) {
            s += xv[i] * sva_s[i * 4 + h];
            d += xv[i] * sva_d[i * 4 + h];
        }
        es[h] = s; ed[h] = d;
    }
    *(float4*)&g_es1[n * 4] = make_float4(es[0], es[1], es[2], es[3]);
    *(float4*)&g_ed1[n * 4] = make_float4(ed[0], ed[1], ed[2], ed[3]);
    float p[4];
    #pragma unroll
    for (int h = 0; h < 4; h++) p[h] = __expf(lrelu(es[h] + ed[h]));
    float a[32];
    #pragma unroll
    for (int h = 0; h < 4; h++) {
        #pragma unroll
        for (int i = 0; i < 7; i++) a[h * 7 + i] = p[h] * xv[i];
        a[28 + h] = p[h];
    }
    #pragma unroll
    for (int q = 0; q < 8; q++)
        *(float4*)&g_acc[n * 32 + q * 4] = make_float4(a[q*4], a[q*4+1], a[q*4+2], a[q*4+3]);
}

// ---------------- K2: layer1 edge aggregation, two-phase ----------------
__global__ __launch_bounds__(256) void k_agg1(
        const float* __restrict__ x, const int* __restrict__ src,
        const int* __restrict__ dst, int E) {
    __shared__ float sp[256 * 4];
    __shared__ int   ssrc[256];
    __shared__ int   sdst[256];
    int t = threadIdx.x;
    int ebase = blockIdx.x << 8;
    int e = ebase + t;
    if (e < E) {
        int s = src[e], d = dst[e];
        const float4 es = *(const float4*)&g_es1[s * 4];
        const float4 ed = *(const float4*)&g_ed1[d * 4];
        sp[t * 4 + 0] = __expf(lrelu(es.x + ed.x));
        sp[t * 4 + 1] = __expf(lrelu(es.y + ed.y));
        sp[t * 4 + 2] = __expf(lrelu(es.z + ed.z));
        sp[t * 4 + 3] = __expf(lrelu(es.w + ed.w));
        ssrc[t] = s; sdst[t] = d;
    }
    __syncthreads();
    int lane = t & 7, eg = t >> 3;
    int eend = min(256, E - ebase);
    #pragma unroll 2
    for (int r = 0; r < 8; r++) {
        int le = eg * 8 + r;
        if (le >= eend) break;
        int s = ssrc[le], d = sdst[le];
        float p[4] = { sp[le*4], sp[le*4+1], sp[le*4+2], sp[le*4+3] };
        const float* xs = &x[s * 7];
        float v[4];
        #pragma unroll
        for (int j = 0; j < 4; j++) {
            int idx = lane * 4 + j;
            int h7 = (idx * 9363) >> 16;  // idx/7 (exact for idx<32)
            int i7 = idx - h7 * 7;
            v[j] = (idx < 28) ? p[h7] * __ldg(&xs[i7]) : p[idx - 28];
        }
        atomicAdd((float4*)&g_acc[d * 32 + lane * 4], make_float4(v[0], v[1], v[2], v[3]));
    }
}

// ---------------- K3: acc -> act1 -> h2 -> logits -> self2 seed ----------------
// 256 thr, 8 warps, 8 nodes/warp (64/block). Weights+acc in registers, shuffles
// replace broadcast LDS in Stage B; Stage C: 1 LDG + 2 broadcast LDS.128 per k for 8 nodes.
__global__ __launch_bounds__(256) void k_finish1(
        const float* __restrict__ W1, const float* __restrict__ b1,
        const float* __restrict__ W2, const float* __restrict__ as2,
        const float* __restrict__ ad2, int N) {
    __shared__ float sactT[128][68];   // [channel][node]; rows 16B-aligned, 4-way STS conflicts
    int t = threadIdx.x;
    int w = t >> 5, lane = t & 31;

    // per-lane weights into registers
    float rW1[4][7], rb1[4];
    #pragma unroll
    for (int q = 0; q < 4; q++) {
        rb1[q] = __ldg(&b1[q * 32 + lane]);
        #pragma unroll
        for (int i = 0; i < 7; i++) rW1[q][i] = __ldg(&W1[i * 128 + q * 32 + lane]);
    }
    float r_as = __ldg(&as2[lane]), r_ad = __ldg(&ad2[lane]);

    int nbase = blockIdx.x * 64 + w * 8;
    // coalesced acc rows into registers
    float racc[8];
    #pragma unroll
    for (int j = 0; j < 8; j++) {
        int n = nbase + j;
        racc[j] = (n < N) ? g_acc[n * 32 + lane] : 1.f;
    }

    // Stage B: act1 via shuffles (no L1 reads)
    #pragma unroll
    for (int j = 0; j < 8; j++) {
        #pragma unroll
        for (int q = 0; q < 4; q++) {
            float s = 0.f;
            #pragma unroll
            for (int i = 0; i < 7; i++)
                s += __shfl_sync(0xFFFFFFFFu, racc[j], q * 7 + i) * rW1[q][i];
            float den = __shfl_sync(0xFFFFFFFFu, racc[j], 28 + q) + 1e-16f;
            sactT[q * 32 + lane][w * 8 + j] = elu(__fdividef(s, den) + rb1[q]);
        }
    }
    __syncwarp();   // warp w writes & reads only columns [w*8, w*8+8)

    // Stage C: h2 = act1 @ W2 for 8 nodes
    float h2a[8] = {0.f,0.f,0.f,0.f,0.f,0.f,0.f,0.f};
    #pragma unroll 4
    for (int k = 0; k < 128; k++) {
        float wv = __ldg(&W2[k * 32 + lane]);
        float4 a0 = *(const float4*)&sactT[k][w * 8];
        float4 a1 = *(const float4*)&sactT[k][w * 8 + 4];
        h2a[0] += a0.x * wv; h2a[1] += a0.y * wv;
        h2a[2] += a0.z * wv; h2a[3] += a0.w * wv;
        h2a[4] += a1.x * wv; h2a[5] += a1.y * wv;
        h2a[6] += a1.z * wv; h2a[7] += a1.w * wv;
    }

    // Epilogue: logits + fused layer2 self-loop seed
    #pragma unroll
    for (int j = 0; j < 8; j++) {
        int n = nbase + j;
        if (n >= N) continue;
        float h2 = h2a[j];
        float e_s = h2 * r_as, e_d = h2 * r_ad;
        #pragma unroll
        for (int o = 16; o; o >>= 1) {
            e_s += __shfl_xor_sync(0xFFFFFFFFu, e_s, o);
            e_d += __shfl_xor_sync(0xFFFFFFFFu, e_d, o);
        }
        float p = __expf(lrelu(e_s + e_d));
        g_h2[n * 32 + lane] = h2;
        g_out2[n * 32 + lane] = p * h2;
        if (lane == 0) { g_es2[n] = e_s; g_ed2[n] = e_d; g_den2[n] = p; }
    }
}

// ---------------- K5: layer2 edge aggregation, two-phase ----------------
__global__ __launch_bounds__(256) void k_agg2(
        const int* __restrict__ src, const int* __restrict__ dst, int E) {
    __shared__ float sp[256];
    __shared__ int   ssrc[256];
    __shared__ int   sdst[256];
    int t = threadIdx.x;
    int ebase = blockIdx.x << 8;
    int e = ebase + t;
    if (e < E) {
        int s = src[e], d = dst[e];
        float p = __expf(lrelu(g_es2[s] + g_ed2[d]));
        atomicAdd(&g_den2[d], p);
        sp[t] = p; ssrc[t] = s; sdst[t] = d;
    }
    __syncthreads();
    int lane = t & 7, eg = t >> 3;
    int eend = min(256, E - ebase);
    #pragma unroll 2
    for (int r = 0; r < 8; r++) {
        int le = eg * 8 + r;
        if (le >= eend) break;
        int s = ssrc[le], d = sdst[le];
        float p = sp[le];
        float4 hv = *(const float4*)&g_h2[s * 32 + lane * 4];
        atomicAdd((float4*)&g_out2[d * 32 + lane * 4],
                  make_float4(hv.x * p, hv.y * p, hv.z * p, hv.w * p));
    }
}

// ---------------- K7: finalize layer2 act, pools ----------------
__global__ void k_pool(const float* __restrict__ b2, const int* __restrict__ batch, int N) {
    int gid = blockIdx.x * blockDim.x + threadIdx.x;
    int n = gid >> 5, c = gid & 31;
    if (n >= N) return;
    float v = elu(__fdividef(g_out2[n * 32 + c], g_den2[n] + 1e-16f) + b2[c]);
    int g = batch[n];
    atomicAdd(&g_msum[g * 32 + c], v);
    atomicMax(&g_mmax[g * 32 + c], fenc(v));
    if (c == 0) atomicAdd(&g_cnt[g], 1.f);
}

// ---------------- K8: readout MLP ----------------
__global__ void k_mlp(const float* __restrict__ Wm1, const float* __restrict__ bm1,
                      const float* __restrict__ Wm2, const float* __restrict__ bm2,
                      float* __restrict__ out) {
    __shared__ float gv[64];
    __shared__ float red[64];
    int g = blockIdx.x, j = threadIdx.x;  // 64
    if (j < 32) gv[j] = g_msum[g * 32 + j] / g_cnt[g];
    else        gv[j] = fdec(g_mmax[g * 32 + (j - 32)]);
    __syncthreads();
    float acc = bm1[j];
    #pragma unroll 8
    for (int i = 0; i < 64; i++) acc += gv[i] * Wm1[i * 64 + j];
    red[j] = fmaxf(acc, 0.f) * Wm2[j];
    __syncthreads();
    for (int o = 32; o; o >>= 1) {
        if (j < o) red[j] += red[j + o];
        __syncthreads();
    }
    if (j == 0) out[g] = red[0] + bm2[0];
}

// ---------------- host ----------------
extern "C" void kernel_launch(void* const* d_in, const int* in_sizes, int n_in,
                              void* d_out, int out_size) {
    const float* x    = (const float*)d_in[0];
    const int*   ei   = (const int*)  d_in[1];
    const int*   bat  = (const int*)  d_in[2];
    const float* W1   = (const float*)d_in[3];
    const float* as1  = (const float*)d_in[4];
    const float* ad1  = (const float*)d_in[5];
    const float* b1   = (const float*)d_in[6];
    const float* W2   = (const float*)d_in[7];
    const float* as2  = (const float*)d_in[8];
    const float* ad2  = (const float*)d_in[9];
    const float* b2   = (const float*)d_in[10];
    const float* Wm1  = (const float*)d_in[11];
    const float* bm1  = (const float*)d_in[12];
    const float* Wm2  = (const float*)d_in[13];
    const float* bm2  = (const float*)d_in[14];
    float* out = (float*)d_out;

    int N = in_sizes[0] / 7;
    int E = in_sizes[1] / 2;
    const int* src = ei;
    const int* dst = ei + E;

    k_node1<<<(N + 255) / 256, 256>>>(x, W1, as1, ad1, N);
    k_agg1<<<(E + 255) / 256, 256>>>(x, src, dst, E);
    k_finish1<<<(N + 63) / 64, 256>>>(W1, b1, W2, as2, ad2, N);
    k_agg2<<<(E + 255) / 256, 256>>>(src, dst, E);
    {
        long long thr = (long long)N * 32;
        k_pool<<<(int)((thr + 255) / 256), 256>>>(b2, bat, N);
    }
    k_mlp<<<GG, 64>>>(Wm1, bm1, Wm2, bm2, out);
}